// round 6
// baseline (speedup 1.0000x reference)
#include <cuda_runtime.h>

#define DD 768
#define NRV 6          // DD / 128  (float4 rows per lane)
#define NE 64          // NUM_ELEMS
#define MAXB 16

// scratch (no allocations allowed)
__device__ int   g_parent_seq[MAXB * NE];
__device__ float g_style_proj[MAXB * DD];
__device__ float g_pfeats[MAXB * NE * DD];   // feats of each (b, elem) parent panel

// ---------------------------------------------------------------------------
// setup: style projection (B x D) and parent_seq init
// ---------------------------------------------------------------------------
__global__ void setup_kernel(const float* __restrict__ sv,
                             const float* __restrict__ sw,
                             const float* __restrict__ sb, int B) {
    int b = blockIdx.x;
    if (b == 0) {
        for (int i = threadIdx.x; i < B * NE; i += blockDim.x)
            g_parent_seq[i] = -1;
    }
    float s0 = sv[b * 4 + 0], s1 = sv[b * 4 + 1];
    float s2 = sv[b * 4 + 2], s3 = sv[b * 4 + 3];
    for (int d = threadIdx.x; d < DD; d += blockDim.x) {
        g_style_proj[b * DD + d] =
            s0 * sw[0 * DD + d] + s1 * sw[1 * DD + d] +
            s2 * sw[2 * DD + d] + s3 * sw[3 * DD + d] + sb[d];
    }
}

// ---------------------------------------------------------------------------
// scan: parent_seq[b,e] = max s with panel at (b,s), element index e
// ---------------------------------------------------------------------------
__global__ void scan_kernel(const int* __restrict__ types,
                            const int* __restrict__ eidx,
                            int S, int total) {
    int i = blockIdx.x * blockDim.x + threadIdx.x;
    if (i >= total) return;
    if (types[i] == 1) {
        int b = i / S;
        int s = i - b * S;
        atomicMax(&g_parent_seq[b * NE + eidx[i]], s);
    }
}

// ---------------------------------------------------------------------------
// vectorized feats: one warp computes LN'd feats of token tk into f4[6]
// ---------------------------------------------------------------------------
__device__ __forceinline__ void warp_feats_v(
    int tk, int b, int lane,
    const int* __restrict__ types, const int* __restrict__ eidx,
    const int* __restrict__ pidx,
    const float* __restrict__ type_emb, const float* __restrict__ index_emb,
    const float* __restrict__ parent_emb,
    const float* __restrict__ ln_g, const float* __restrict__ ln_b,
    float4* f4) {
    const float* te = type_emb + types[tk] * DD;
    const float* ie = index_emb + eidx[tk] * DD;
    const float* pe = parent_emb + pidx[tk] * DD;
    const float* sp = g_style_proj + b * DD;
    float sum = 0.f, sq = 0.f;
#pragma unroll
    for (int r = 0; r < NRV; r++) {
        int d = 4 * lane + 128 * r;
        float4 a  = *(const float4*)(te + d);
        float4 bb = *(const float4*)(ie + d);
        float4 c  = *(const float4*)(pe + d);
        float4 s  = *(const float4*)(sp + d);
        float4 x;
        x.x = a.x + bb.x + c.x + s.x;
        x.y = a.y + bb.y + c.y + s.y;
        x.z = a.z + bb.z + c.z + s.z;
        x.w = a.w + bb.w + c.w + s.w;
        f4[r] = x;
        sum += x.x + x.y + x.z + x.w;
        sq  += x.x * x.x + x.y * x.y + x.z * x.z + x.w * x.w;
    }
#pragma unroll
    for (int o = 16; o; o >>= 1) {
        sum += __shfl_xor_sync(0xffffffffu, sum, o);
        sq  += __shfl_xor_sync(0xffffffffu, sq, o);
    }
    float mean = sum * (1.0f / DD);
    float var  = sq * (1.0f / DD) - mean * mean;
    float rstd = rsqrtf(var + 1e-5f);
#pragma unroll
    for (int r = 0; r < NRV; r++) {
        int d = 4 * lane + 128 * r;
        float4 g  = *(const float4*)(ln_g + d);
        float4 bo = *(const float4*)(ln_b + d);
        float4 x = f4[r];
        x.x = (x.x - mean) * rstd * g.x + bo.x;
        x.y = (x.y - mean) * rstd * g.y + bo.y;
        x.z = (x.z - mean) * rstd * g.z + bo.z;
        x.w = (x.w - mean) * rstd * g.w + bo.w;
        f4[r] = x;
    }
}

// ---------------------------------------------------------------------------
// prefeats: compute feats of each distinct parent panel (<= B*NE of them)
// ---------------------------------------------------------------------------
__global__ void prefeats_kernel(const int* __restrict__ types,
                                const int* __restrict__ eidx,
                                const int* __restrict__ pidx,
                                const float* __restrict__ type_emb,
                                const float* __restrict__ index_emb,
                                const float* __restrict__ parent_emb,
                                const float* __restrict__ ln_g,
                                const float* __restrict__ ln_b,
                                int Bv, int Sv) {
    int wid  = (blockIdx.x * blockDim.x + threadIdx.x) >> 5;
    int lane = threadIdx.x & 31;
    if (wid >= Bv * NE) return;
    int b  = wid / NE;
    int ps = g_parent_seq[wid];
    if (ps < 0) return;
    float4 f4[NRV];
    warp_feats_v(b * Sv + ps, b, lane, types, eidx, pidx, type_emb, index_emb,
                 parent_emb, ln_g, ln_b, f4);
    float* row = g_pfeats + (size_t)wid * DD;
#pragma unroll
    for (int r = 0; r < NRV; r++)
        *(float4*)(row + 4 * lane + 128 * r) = f4[r];
}

// ---------------------------------------------------------------------------
__device__ __forceinline__ void reduce8(float* a) {
#pragma unroll
    for (int o = 16; o; o >>= 1) {
#pragma unroll
        for (int j = 0; j < 8; j++) a[j] += __shfl_xor_sync(0xffffffffu, a[j], o);
    }
}

__device__ __forceinline__ void reduce4(float* a) {
#pragma unroll
    for (int o = 16; o; o >>= 1) {
#pragma unroll
        for (int j = 0; j < 4; j++) a[j] += __shfl_xor_sync(0xffffffffu, a[j], o);
    }
}

// ---------------------------------------------------------------------------
// fused main kernel: one warp per token
// ---------------------------------------------------------------------------
__global__ void __launch_bounds__(128)
main_kernel(const int* __restrict__ types, const int* __restrict__ eidx,
            const int* __restrict__ pidx,
            const float* __restrict__ type_emb,
            const float* __restrict__ index_emb,
            const float* __restrict__ parent_emb,
            const float* __restrict__ ln_g, const float* __restrict__ ln_b,
            const float* __restrict__ panel_w, const float* __restrict__ panel_b,
            const float* __restrict__ dialog_w, const float* __restrict__ dialog_b,
            const float* __restrict__ char_w, const float* __restrict__ char_b,
            float* __restrict__ out_panel, float* __restrict__ out_dialog,
            float* __restrict__ out_char, int Bv, int Sv) {
    int wid  = (blockIdx.x * blockDim.x + threadIdx.x) >> 5;
    int lane = threadIdx.x & 31;
    int total = Bv * Sv;
    if (wid >= total) return;
    int tk = wid;
    int b  = tk / Sv;
    int t  = types[tk];

    float* po = out_panel  + tk * 8;
    float* dq = out_dialog + tk * 8;
    float* co = out_char   + tk * 4;
    const float4 z4 = make_float4(0.f, 0.f, 0.f, 0.f);

    int valid_child = 0;
    int prow = 0;
    if (t >= 2) {
        prow = b * NE + pidx[tk];
        valid_child = (g_parent_seq[prow] >= 0);
    }

    if (t == 0 || (t >= 2 && !valid_child)) {
        if (lane == 0) {
            *(float4*)po = z4; *(float4*)(po + 4) = z4;
            *(float4*)dq = z4; *(float4*)(dq + 4) = z4;
            *(float4*)co = z4;
        }
        return;
    }

    float4 f4[NRV];
    warp_feats_v(tk, b, lane, types, eidx, pidx, type_emb, index_emb, parent_emb,
                 ln_g, ln_b, f4);
    const float* fs = (const float*)f4;

    if (t == 1) {  // PANEL head
        float a[8] = {0.f, 0.f, 0.f, 0.f, 0.f, 0.f, 0.f, 0.f};
#pragma unroll
        for (int r = 0; r < NRV; r++) {
#pragma unroll
            for (int i = 0; i < 4; i++) {
                int d = 4 * lane + 128 * r + i;
                float x = fs[4 * r + i];
                float4 w0 = *(const float4*)(panel_w + d * 8);
                float4 w1 = *(const float4*)(panel_w + d * 8 + 4);
                a[0] += x * w0.x; a[1] += x * w0.y; a[2] += x * w0.z; a[3] += x * w0.w;
                a[4] += x * w1.x; a[5] += x * w1.y; a[6] += x * w1.z; a[7] += x * w1.w;
            }
        }
        reduce8(a);
        if (lane == 0) {
            float4 b0 = *(const float4*)(panel_b);
            float4 b1 = *(const float4*)(panel_b + 4);
            *(float4*)po = make_float4(a[0] + b0.x, a[1] + b0.y, a[2] + b0.z, a[3] + b0.w);
            *(float4*)(po + 4) = make_float4(a[4] + b1.x, a[5] + b1.y, a[6] + b1.z, a[7] + b1.w);
            *(float4*)dq = z4; *(float4*)(dq + 4) = z4;
            *(float4*)co = z4;
        }
        return;
    }

    // child token: read precomputed parent feats from L2-resident table
    const float* pfrow = g_pfeats + (size_t)prow * DD;

    if (t == 2) {  // DIALOG head: [f, pf] @ dialog_w(1536,8)
        float a[8] = {0.f, 0.f, 0.f, 0.f, 0.f, 0.f, 0.f, 0.f};
#pragma unroll
        for (int r = 0; r < NRV; r++) {
            float4 pf = *(const float4*)(pfrow + 4 * lane + 128 * r);
            const float* pfi = (const float*)&pf;
#pragma unroll
            for (int i = 0; i < 4; i++) {
                int d = 4 * lane + 128 * r + i;
                float x = fs[4 * r + i];
                float y = pfi[i];
                float4 w0 = *(const float4*)(dialog_w + d * 8);
                float4 w1 = *(const float4*)(dialog_w + d * 8 + 4);
                float4 v0 = *(const float4*)(dialog_w + (DD + d) * 8);
                float4 v1 = *(const float4*)(dialog_w + (DD + d) * 8 + 4);
                a[0] += x * w0.x + y * v0.x; a[1] += x * w0.y + y * v0.y;
                a[2] += x * w0.z + y * v0.z; a[3] += x * w0.w + y * v0.w;
                a[4] += x * w1.x + y * v1.x; a[5] += x * w1.y + y * v1.y;
                a[6] += x * w1.z + y * v1.z; a[7] += x * w1.w + y * v1.w;
            }
        }
        reduce8(a);
        if (lane == 0) {
            float4 b0 = *(const float4*)(dialog_b);
            float4 b1 = *(const float4*)(dialog_b + 4);
            *(float4*)dq = make_float4(a[0] + b0.x, a[1] + b0.y, a[2] + b0.z, a[3] + b0.w);
            *(float4*)(dq + 4) = make_float4(a[4] + b1.x, a[5] + b1.y, a[6] + b1.z, a[7] + b1.w);
            *(float4*)po = z4; *(float4*)(po + 4) = z4;
            *(float4*)co = z4;
        }
    } else {  // CHAR head: [f, pf] @ char_w(1536,4)
        float a[4] = {0.f, 0.f, 0.f, 0.f};
#pragma unroll
        for (int r = 0; r < NRV; r++) {
            float4 pf = *(const float4*)(pfrow + 4 * lane + 128 * r);
            const float* pfi = (const float*)&pf;
#pragma unroll
            for (int i = 0; i < 4; i++) {
                int d = 4 * lane + 128 * r + i;
                float x = fs[4 * r + i];
                float y = pfi[i];
                float4 w0 = *(const float4*)(char_w + d * 4);
                float4 v0 = *(const float4*)(char_w + (DD + d) * 4);
                a[0] += x * w0.x + y * v0.x; a[1] += x * w0.y + y * v0.y;
                a[2] += x * w0.z + y * v0.z; a[3] += x * w0.w + y * v0.w;
            }
        }
        reduce4(a);
        if (lane == 0) {
            float4 b0 = *(const float4*)(char_b);
            *(float4*)co = make_float4(a[0] + b0.x, a[1] + b0.y, a[2] + b0.z, a[3] + b0.w);
            *(float4*)po = z4; *(float4*)(po + 4) = z4;
            *(float4*)dq = z4; *(float4*)(dq + 4) = z4;
        }
    }
}

// ---------------------------------------------------------------------------
extern "C" void kernel_launch(void* const* d_in, const int* in_sizes, int n_in,
                              void* d_out, int out_size) {
    const int*   types     = (const int*)d_in[0];
    const int*   eidx      = (const int*)d_in[1];
    const int*   pidx      = (const int*)d_in[2];
    const float* style_v   = (const float*)d_in[3];
    const float* type_emb  = (const float*)d_in[4];
    const float* index_emb = (const float*)d_in[5];
    const float* parent_emb= (const float*)d_in[6];
    const float* style_w   = (const float*)d_in[7];
    const float* style_b   = (const float*)d_in[8];
    const float* ln_g      = (const float*)d_in[9];
    const float* ln_b      = (const float*)d_in[10];
    const float* panel_w   = (const float*)d_in[11];
    const float* panel_b   = (const float*)d_in[12];
    const float* dialog_w  = (const float*)d_in[13];
    const float* dialog_b  = (const float*)d_in[14];
    const float* char_w    = (const float*)d_in[15];
    const float* char_b    = (const float*)d_in[16];

    int B = in_sizes[3] / 4;
    int S = in_sizes[0] / B;
    int total = B * S;

    float* out_panel  = (float*)d_out;
    float* out_dialog = out_panel + (size_t)total * 8;
    float* out_char   = out_dialog + (size_t)total * 8;

    setup_kernel<<<B, 256>>>(style_v, style_w, style_b, B);
    scan_kernel<<<(total + 255) / 256, 256>>>(types, eidx, S, total);

    int pwarps = B * NE;                       // <= 1024 parent slots
    prefeats_kernel<<<(pwarps * 32 + 255) / 256, 256>>>(
        types, eidx, pidx, type_emb, index_emb, parent_emb, ln_g, ln_b, B, S);

    int blocks = (total * 32 + 127) / 128;     // one warp per token, 4 warps/block
    main_kernel<<<blocks, 128>>>(types, eidx, pidx, type_emb, index_emb,
                                 parent_emb, ln_g, ln_b, panel_w, panel_b,
                                 dialog_w, dialog_b, char_w, char_b,
                                 out_panel, out_dialog, out_char, B, S);
}